// round 16
// baseline (speedup 1.0000x reference)
#include <cuda_runtime.h>
#include <math.h>

#define Bsz 8
#define Cc 64
#define HWd 128
#define NPIX (HWd*HWd)
#define PLANE ((size_t)Cc*NPIX)
#define BS ((size_t)Bsz*Cc*NPIX)
#define LEAKv 0.2f
#define CLAMPv 0.8f
#define EPSv 1e-5f
#define CWS (64*64*9)

#define CTW 16
#define CTH 8
#define INC 18
#define INREAL 180
#define INPAD 196
#define WPAD 68
#define SW_CH (36*WPAD)
#define WSET 18432

// ---------------- scratch ----------------
__device__ float g_x1[Bsz*Cc*NPIX];
__device__ float g_x2[Bsz*Cc*NPIX];
__device__ float g_y1[Bsz*Cc*NPIX];
__device__ float g_y2[Bsz*Cc*NPIX];
__device__ float g_rb[Bsz*Cc*NPIX];
__device__ float g_sb[Bsz*Cc*NPIX];
__device__ float g_xf[Bsz*Cc*NPIX];
__device__ float g_hb[Bsz*Cc*NPIX];
__device__ float g_gv[Bsz*Cc];
__device__ int   g_sel[Bsz*2];
__device__ float g_cofsel[Bsz*2];
__device__ uint2 g_wpack[14*WSET];
__device__ float2 g_part[Bsz*128*64];

__device__ __forceinline__ unsigned f2tf32(float f) {
    unsigned r;
    asm("cvt.rna.tf32.f32 %0, %1;" : "=r"(r) : "f"(f));
    return r;
}

__device__ __forceinline__ void mma_tf32(float* d, const unsigned* a, const unsigned* b) {
    asm volatile(
        "mma.sync.aligned.m16n8k8.row.col.f32.tf32.tf32.f32 "
        "{%0,%1,%2,%3}, {%4,%5,%6,%7}, {%8,%9}, {%0,%1,%2,%3};"
        : "+f"(d[0]), "+f"(d[1]), "+f"(d[2]), "+f"(d[3])
        : "r"(a[0]), "r"(a[1]), "r"(a[2]), "r"(a[3]), "r"(b[0]), "r"(b[1]));
}

__device__ __forceinline__ void cp_async8(unsigned sdst, const void* gsrc) {
    asm volatile("cp.async.ca.shared.global [%0], [%1], 8;" :: "r"(sdst), "l"(gsrc));
}
__device__ __forceinline__ void cp_commit() { asm volatile("cp.async.commit_group;" ::: "memory"); }
__device__ __forceinline__ void cp_wait1()  { asm volatile("cp.async.wait_group 1;" ::: "memory"); }
__device__ __forceinline__ void cp_wait0()  { asm volatile("cp.async.wait_group 0;" ::: "memory"); }

// ---------------- single merged weight repack ----------------
__global__ void pack_all(const float* __restrict__ w1, const float* __restrict__ w2,
                         const float* __restrict__ e1, const float* __restrict__ e2,
                         uint2* __restrict__ dst)
{
    int i = blockIdx.x*blockDim.x + threadIdx.x;
    if (i >= 14*WSET) return;
    int s = i / WSET;
    int r = i % WSET;
    const float* src;
    if (s < 3)       src = w1 + (size_t)s * CWS;
    else if (s < 6)  src = w2 + (size_t)(s-3) * CWS;
    else if (s < 10) src = e1 + (size_t)(s-6) * CWS;
    else             src = e2 + (size_t)(s-10) * CWS;
    int ck  = r / 2304;
    int rem = r % 2304;
    int q = rem >> 6, oc = rem & 63;
    int kq = q & 3, tap = q >> 2;
    int ic = ck*8 + kq;
    dst[i] = make_uint2(f2tf32(src[(oc*64 + ic)*9 + tap]),
                        f2tf32(src[(oc*64 + ic + 4)*9 + tap]));
}

// ---------------- 3x3 conv: TF32 MMA (frozen core) ----------------
// MODE 0: out = conv+bias
// MODE 1: out = conv+bias+add1+add2
// MODE 2: out = conv+bias+add1
// MODE 3: out = conv+bias+add1 + add2*exp(clamp*(2sig(spre)-1))
// MODE 4: MERGED expert conv1: z=(slot*8+b); dst[slot] = cof*lrelu(conv+b_e)
// MODE 5: MERGED expert conv2: K=128 (in: 0-7, add2: 8-15), weights e0/e1 per half
// MODE 6: DUAL conv1: z=(set*8+b); weights = wpk - set*WSET, bias = bias - set*Cc;
//         dst = set ? out2 : out   (plain conv+bias)
template<int MODE>
__global__ __launch_bounds__(256, 3)
void conv3x3_mma(const float* __restrict__ in, const uint2* __restrict__ wpk,
                 const float* __restrict__ bias, float* __restrict__ out,
                 const float* __restrict__ add1, const float* __restrict__ add2,
                 const float* __restrict__ spre,
                 const int* __restrict__ sel, const float* __restrict__ cofsel,
                 float* __restrict__ out2)
{
    __shared__ uint2 s_in[4 * INPAD];
    __shared__ uint2 s_w[2 * SW_CH];

    const int NCK = (MODE == 5) ? 16 : 8;

    int tid = threadIdx.x;
    int wid = tid >> 5;
    int lane = tid & 31;
    int l4 = lane & 3;
    int g  = lane >> 2;
    int warp_m = wid & 3;
    int warp_n = wid >> 2;
    int wm2 = warp_m * 2;
    int n0 = warp_n * 32;

    int bz = blockIdx.z;
    int b    = (MODE == 4 || MODE == 6) ? (bz & 7) : bz;
    int slot = (MODE == 4 || MODE == 6) ? (bz >> 3) : 0;
    int w0 = blockIdx.x * CTW;
    int h0 = blockIdx.y * CTH;

    const uint2* wp  = wpk;
    const uint2* wp1 = nullptr;
    const float* bbase  = bias;
    const float* bbase1 = nullptr;
    float cw = 1.f, c0 = 0.f, c1 = 0.f;
    if (MODE == 4) {
        int e = sel[b*2 + slot];
        wp = wpk + e * WSET;
        bbase = bias + e * Cc;
        cw = cofsel[b*2 + slot];
    }
    if (MODE == 6) {
        wp = wpk - slot * WSET;      // base idx 2; slot1 -> idx 1
        bbase = bias - slot * Cc;
    }
    if (MODE == 5) {
        int e0 = sel[b*2], e1 = sel[b*2 + 1];
        wp  = wpk + e0 * WSET;
        wp1 = wpk + e1 * WSET;
        bbase  = bias + e0 * Cc;
        bbase1 = bias + e1 * Cc;
        c0 = cofsel[b*2]; c1 = cofsel[b*2 + 1];
    }
    const float* inb0 = in + (size_t)b * PLANE;
    const float* inb1 = (MODE == 5) ? (add2 + (size_t)b * PLANE) : nullptr;

    unsigned wdst8[9];
    unsigned wsrc[9];
    unsigned swbase = (unsigned)__cvta_generic_to_shared(s_w);
    #pragma unroll
    for (int t = 0; t < 9; t++) {
        int i = tid + t*256;
        int q = i >> 6, oc = i & 63;
        wdst8[t] = (unsigned)((q*WPAD + oc) * 8);
        wsrc[t] = (unsigned)(q*64 + oc);
    }

    bool iact[3], ival[3];
    unsigned ioff[3];
    int ismem[3];
    #pragma unroll
    for (int t = 0; t < 3; t++) {
        int i = tid + t*256;
        iact[t] = (i < 4*INREAL);
        int kq  = i / INREAL;
        int rem = i - kq*INREAL;
        int rr = rem / INC;
        int cc = rem - rr*INC;
        int h = h0 - 1 + rr;
        int w = w0 - 1 + cc;
        ival[t] = iact[t] && ((unsigned)h < HWd) && ((unsigned)w < HWd);
        ismem[t] = kq*INPAD + rem;
        ioff[t] = ival[t] ? (unsigned)(kq*NPIX + h*HWd + w) : 0u;
    }

    float d[2][4][4];
    #pragma unroll
    for (int mt = 0; mt < 2; mt++)
        #pragma unroll
        for (int nt = 0; nt < 4; nt++)
            #pragma unroll
            for (int r = 0; r < 4; r++) d[mt][nt][r] = 0.f;

    #pragma unroll
    for (int t = 0; t < 9; t++)
        cp_async8(swbase + wdst8[t], wp + wsrc[t]);
    cp_commit();

    float ipf0[3], ipf1[3];
    #pragma unroll
    for (int t = 0; t < 3; t++) {
        ipf0[t] = ival[t] ? inb0[ioff[t]] : 0.f;
        ipf1[t] = ival[t] ? inb0[ioff[t] + 4*NPIX] : 0.f;
    }

    #pragma unroll 1
    for (int ck = 0; ck < NCK; ck++) {
        __syncthreads();
        #pragma unroll
        for (int t = 0; t < 3; t++)
            if (iact[t]) s_in[ismem[t]] = make_uint2(f2tf32(ipf0[t]), f2tf32(ipf1[t]));
        if (ck < NCK-1) {
            int nx = ck + 1;
            unsigned bufoff = (unsigned)((nx & 1) * SW_CH * 8);
            const uint2* srcw = ((MODE == 5 && nx >= 8) ? wp1 : wp) + (nx & 7) * 2304;
            #pragma unroll
            for (int t = 0; t < 9; t++)
                cp_async8(swbase + bufoff + wdst8[t], srcw + wsrc[t]);
            cp_commit();
            const float* srci = (MODE == 5 && nx >= 8) ? inb1 : inb0;
            unsigned ib = (unsigned)((nx & 7) * 8*NPIX);
            #pragma unroll
            for (int t = 0; t < 3; t++) {
                if (ival[t]) {
                    ipf0[t] = srci[ioff[t] + ib];
                    ipf1[t] = srci[ioff[t] + ib + 4*NPIX];
                }
            }
            cp_wait1();
        } else {
            cp_wait0();
        }
        __syncthreads();

        const uint2* swc = s_w + (ck&1)*SW_CH;
        #pragma unroll
        for (int tap = 0; tap < 9; tap++) {
            int ky = tap / 3, kx = tap % 3;
            int abase = l4*INPAD + (wm2 + ky)*INC + kx + g;
            unsigned a[2][4];
            #pragma unroll
            for (int mt = 0; mt < 2; mt++) {
                uint2 p0 = s_in[abase + mt*INC];
                uint2 p1 = s_in[abase + mt*INC + 8];
                a[mt][0] = p0.x; a[mt][1] = p1.x; a[mt][2] = p0.y; a[mt][3] = p1.y;
            }
            int bb = (tap*4 + l4)*WPAD + n0 + g;
            unsigned bq[4][2];
            #pragma unroll
            for (int nt = 0; nt < 4; nt++) {
                uint2 q = swc[bb + nt*8];
                bq[nt][0] = q.x; bq[nt][1] = q.y;
            }
            #pragma unroll
            for (int mt = 0; mt < 2; mt++)
                #pragma unroll
                for (int nt = 0; nt < 4; nt++)
                    mma_tf32(d[mt][nt], a[mt], bq[nt]);
        }
    }

    float csum = c0 + c1;
    float* dstp = out;
    if (MODE == 4 && slot) dstp = out2;
    if (MODE == 6 && slot) dstp = out2;
    #pragma unroll
    for (int mt = 0; mt < 2; mt++) {
        int h = h0 + wm2 + mt;
        #pragma unroll
        for (int nt = 0; nt < 4; nt++) {
            int oc = n0 + nt*8 + l4*2;
            float bv0, bv1;
            if (MODE == 5) {
                bv0 = c0*bbase[oc]   + c1*bbase1[oc];
                bv1 = c0*bbase[oc+1] + c1*bbase1[oc+1];
            } else {
                bv0 = bbase[oc]; bv1 = bbase[oc+1];
            }
            size_t p0 = (size_t)b*PLANE + (size_t)oc*NPIX + (size_t)h*HWd;
            size_t p1 = p0 + NPIX;
            int wa = w0 + g, wb2 = wa + 8;
            float vv[4] = { d[mt][nt][0] + bv0, d[mt][nt][1] + bv1,
                            d[mt][nt][2] + bv0, d[mt][nt][3] + bv1 };
            size_t ix[4] = { p0 + wa, p1 + wa, p0 + wb2, p1 + wb2 };
            #pragma unroll
            for (int r = 0; r < 4; r++) {
                size_t idx = ix[r];
                float v = vv[r];
                if (MODE == 1) {
                    v += add1[idx] + add2[idx];
                } else if (MODE == 2) {
                    v += add1[idx];
                } else if (MODE == 3) {
                    float sp = spre[idx];
                    float sig = 1.f / (1.f + expf(-sp));
                    float s = CLAMPv * (2.f*sig - 1.f);
                    v += add1[idx] + add2[idx] * expf(s);
                } else if (MODE == 4) {
                    v = v > 0.f ? v : LEAKv * v;
                    v *= cw;
                } else if (MODE == 5) {
                    v += csum * add1[idx];
                }
                dstp[idx] = v;
            }
        }
    }
}

// ---------------- 1x1 GEMM via TF32 MMA (+ compile-time POOL partials) ----------------
#define GPAD 132

template<int IC, bool POOL>
__global__ __launch_bounds__(256)
void gemm1x1_mma(const float* __restrict__ inA, const float* __restrict__ inB,
                 const float* __restrict__ W, const float* __restrict__ bias,
                 float* __restrict__ outA, float* __restrict__ outB,
                 float2* __restrict__ gpart)
{
    __shared__ uint2 s_x[8 * GPAD];
    __shared__ uint2 s_w[8 * WPAD];
    __shared__ float spm[8*32], sps[8*32];

    const int NCK = IC / 16;

    int tid = threadIdx.x;
    int wid = tid >> 5;
    int lane = tid & 31;
    int l4 = lane & 3;
    int g  = lane >> 2;
    int warp_m = wid & 3;
    int warp_n = wid >> 2;
    int n0 = warp_n * 32;

    int b   = blockIdx.z;
    int oc0 = blockIdx.y * 64;
    int p0  = blockIdx.x * 128;

    int axsm[4];
    unsigned aoff[4];
    #pragma unroll
    for (int t = 0; t < 4; t++) {
        int i = tid + t*256;
        int q = i >> 7, p = i & 127;
        int qoff = (q >> 2)*8 + (q & 3);
        axsm[t] = q*GPAD + p;
        aoff[t] = (unsigned)(qoff*NPIX + p0 + p);
    }
    int wxsm[2];
    unsigned woff0[2];
    #pragma unroll
    for (int t = 0; t < 2; t++) {
        int i = tid + t*256;
        int q = i & 7, oc = i >> 3;
        int qoff = (q >> 2)*8 + (q & 3);
        wxsm[t] = q*WPAD + oc;
        woff0[t] = (unsigned)((oc0 + oc)*IC + qoff);
    }

    const float* baseA = inA + ((size_t)b * (inB ? PLANE : (size_t)IC*NPIX));
    const float* baseB = inB ? (inB + (size_t)b * PLANE) : nullptr;

    float d[2][4][4];
    #pragma unroll
    for (int mt = 0; mt < 2; mt++)
        #pragma unroll
        for (int nt = 0; nt < 4; nt++)
            #pragma unroll
            for (int r = 0; r < 4; r++) d[mt][nt][r] = 0.f;

    float apf0[4], apf1[4], wpf0[2], wpf1[2];
    {
        const float* src = baseA;
        #pragma unroll
        for (int t = 0; t < 4; t++) {
            apf0[t] = src[aoff[t]];
            apf1[t] = src[aoff[t] + 4*NPIX];
        }
        #pragma unroll
        for (int t = 0; t < 2; t++) {
            wpf0[t] = W[woff0[t]];
            wpf1[t] = W[woff0[t] + 4];
        }
    }

    #pragma unroll 1
    for (int ck = 0; ck < NCK; ck++) {
        __syncthreads();
        #pragma unroll
        for (int t = 0; t < 4; t++)
            s_x[axsm[t]] = make_uint2(f2tf32(apf0[t]), f2tf32(apf1[t]));
        #pragma unroll
        for (int t = 0; t < 2; t++)
            s_w[wxsm[t]] = make_uint2(f2tf32(wpf0[t]), f2tf32(wpf1[t]));
        if (ck < NCK-1) {
            int nx = ck + 1;
            const float* src = (baseB && nx >= 4) ? baseB : baseA;
            unsigned chrel;
            if (baseB) chrel = (unsigned)(((nx & 3) * 16) * NPIX);
            else       chrel = (unsigned)(nx * 16 * NPIX);
            #pragma unroll
            for (int t = 0; t < 4; t++) {
                apf0[t] = src[chrel + aoff[t]];
                apf1[t] = src[chrel + aoff[t] + 4*NPIX];
            }
            unsigned wb = (unsigned)(nx * 16);
            #pragma unroll
            for (int t = 0; t < 2; t++) {
                wpf0[t] = W[woff0[t] + wb];
                wpf1[t] = W[woff0[t] + wb + 4];
            }
        }
        __syncthreads();

        #pragma unroll
        for (int ks = 0; ks < 2; ks++) {
            int abase = (ks*4 + l4)*GPAD + warp_m*32 + g;
            unsigned a[2][4];
            #pragma unroll
            for (int mt = 0; mt < 2; mt++) {
                uint2 q0 = s_x[abase + mt*16];
                uint2 q1 = s_x[abase + mt*16 + 8];
                a[mt][0] = q0.x; a[mt][1] = q1.x; a[mt][2] = q0.y; a[mt][3] = q1.y;
            }
            int bb = (ks*4 + l4)*WPAD + n0 + g;
            unsigned bq[4][2];
            #pragma unroll
            for (int nt = 0; nt < 4; nt++) {
                uint2 q = s_w[bb + nt*8];
                bq[nt][0] = q.x; bq[nt][1] = q.y;
            }
            #pragma unroll
            for (int mt = 0; mt < 2; mt++)
                #pragma unroll
                for (int nt = 0; nt < 4; nt++)
                    mma_tf32(d[mt][nt], a[mt], bq[nt]);
        }
    }

    float pm[4][2], ps[4][2];
    if (POOL) {
        #pragma unroll
        for (int nt = 0; nt < 4; nt++)
            #pragma unroll
            for (int j = 0; j < 2; j++) { pm[nt][j] = -1e30f; ps[nt][j] = 0.f; }
    }

    #pragma unroll
    for (int mt = 0; mt < 2; mt++) {
        #pragma unroll
        for (int nt = 0; nt < 4; nt++) {
            int oc = oc0 + n0 + nt*8 + l4*2;
            float bv0 = bias ? bias[oc] : 0.f;
            float bv1 = bias ? bias[oc+1] : 0.f;
            float* dst = outA;
            int ocd = oc;
            if (outB != nullptr && oc >= 64) { dst = outB; ocd = oc - 64; }
            int pix = p0 + warp_m*32 + mt*16 + g;
            size_t q0 = (size_t)b*PLANE + (size_t)ocd*NPIX + pix;
            size_t q1 = q0 + NPIX;
            float v0 = d[mt][nt][0] + bv0;
            float v1 = d[mt][nt][1] + bv1;
            float v2 = d[mt][nt][2] + bv0;
            float v3 = d[mt][nt][3] + bv1;
            dst[q0]     = v0;
            dst[q1]     = v1;
            dst[q0 + 8] = v2;
            dst[q1 + 8] = v3;
            if (POOL) {
                pm[nt][0] = fmaxf(pm[nt][0], fmaxf(v0, v2));
                pm[nt][1] = fmaxf(pm[nt][1], fmaxf(v1, v3));
                ps[nt][0] += v0 + v2;
                ps[nt][1] += v1 + v3;
            }
        }
    }

    if (POOL) {
        #pragma unroll
        for (int m = 4; m <= 16; m <<= 1) {
            #pragma unroll
            for (int nt = 0; nt < 4; nt++)
                #pragma unroll
                for (int j = 0; j < 2; j++) {
                    pm[nt][j] = fmaxf(pm[nt][j], __shfl_xor_sync(0xFFFFFFFF, pm[nt][j], m));
                    ps[nt][j] += __shfl_xor_sync(0xFFFFFFFF, ps[nt][j], m);
                }
        }
        if (g == 0) {
            #pragma unroll
            for (int nt = 0; nt < 4; nt++)
                #pragma unroll
                for (int j = 0; j < 2; j++) {
                    int ol = nt*8 + l4*2 + j;
                    spm[wid*32 + ol] = pm[nt][j];
                    sps[wid*32 + ol] = ps[nt][j];
                }
        }
        __syncthreads();
        if (tid < 64) {
            int oc = tid;
            int wn = oc >> 5, ol = oc & 31;
            float mx = -1e30f, sm = 0.f;
            #pragma unroll
            for (int wm = 0; wm < 4; wm++) {
                mx = fmaxf(mx, spm[(wn*4 + wm)*32 + ol]);
                sm += sps[(wn*4 + wm)*32 + ol];
            }
            gpart[((size_t)b*128 + blockIdx.x)*64 + oc] = make_float2(mx, sm);
        }
    }
}

// ---------------- pool partial reduce ----------------
__global__ __launch_bounds__(128)
void pool2_k(const float2* __restrict__ part, float* __restrict__ gv)
{
    int bidx = blockIdx.x;
    int b = bidx >> 6, oc = bidx & 63;
    int tid = threadIdx.x;
    float2 v = part[((size_t)b*128 + tid)*64 + oc];
    __shared__ float smx[128], ssm[128];
    smx[tid] = v.x; ssm[tid] = v.y;
    __syncthreads();
    for (int st = 64; st; st >>= 1) {
        if (tid < st) { smx[tid] = fmaxf(smx[tid], smx[tid+st]); ssm[tid] += ssm[tid+st]; }
        __syncthreads();
    }
    if (tid == 0) gv[bidx] = smx[0] + ssm[0] * (1.f/NPIX);
}

// ---------------- instance norm (single tensor, block set 0) ----------------
__global__ __launch_bounds__(256)
void inorm_k(float* __restrict__ r, const float* __restrict__ nw, const float* __restrict__ nb)
{
    int bidx = blockIdx.x;
    int b = bidx >> 5, c = bidx & 31;
    float4* p = (float4*)(r + (size_t)b*PLANE + (size_t)c*NPIX);
    int tid = threadIdx.x;
    float4 v[16];
    #pragma unroll
    for (int t = 0; t < 16; t++) v[t] = p[tid + t*256];
    float s = 0.f, s2 = 0.f;
    #pragma unroll
    for (int t = 0; t < 16; t++) {
        s  += (v[t].x + v[t].y) + (v[t].z + v[t].w);
        s2 += (v[t].x*v[t].x + v[t].y*v[t].y) + (v[t].z*v[t].z + v[t].w*v[t].w);
    }
    __shared__ float sh[256], sh2[256];
    sh[tid] = s; sh2[tid] = s2;
    __syncthreads();
    for (int st = 128; st; st >>= 1) {
        if (tid < st) { sh[tid] += sh[tid+st]; sh2[tid] += sh2[tid+st]; }
        __syncthreads();
    }
    float mean = sh[0] * (1.f/NPIX);
    float var = sh2[0] * (1.f/NPIX) - mean*mean;
    float inv = rsqrtf(var + EPSv);
    float sc = inv * nw[c];
    float sh_ = nb[c] - mean * sc;
    #pragma unroll
    for (int t = 0; t < 16; t++) {
        float4 u = v[t];
        u.x = fmaf(u.x, sc, sh_);
        u.y = fmaf(u.y, sc, sh_);
        u.z = fmaf(u.z, sc, sh_);
        u.w = fmaf(u.w, sc, sh_);
        p[tid + t*256] = u;
    }
}

// ---------------- merged instance norm: r0 with set 2 params, r1 with set 1 ----------------
__global__ __launch_bounds__(256)
void inorm2_k(float* __restrict__ r0, float* __restrict__ r1,
              const float* __restrict__ nw, const float* __restrict__ nb)
{
    int bidx = blockIdx.x;         // 0..511
    int half = bidx >> 8;
    int b = (bidx >> 5) & 7;
    int c = bidx & 31;
    float* base = half ? r1 : r0;
    int prm = (half ? 1 : 2) * 32 + c;
    float4* p = (float4*)(base + (size_t)b*PLANE + (size_t)c*NPIX);
    int tid = threadIdx.x;
    float4 v[16];
    #pragma unroll
    for (int t = 0; t < 16; t++) v[t] = p[tid + t*256];
    float s = 0.f, s2 = 0.f;
    #pragma unroll
    for (int t = 0; t < 16; t++) {
        s  += (v[t].x + v[t].y) + (v[t].z + v[t].w);
        s2 += (v[t].x*v[t].x + v[t].y*v[t].y) + (v[t].z*v[t].z + v[t].w*v[t].w);
    }
    __shared__ float sh[256], sh2[256];
    sh[tid] = s; sh2[tid] = s2;
    __syncthreads();
    for (int st = 128; st; st >>= 1) {
        if (tid < st) { sh[tid] += sh[tid+st]; sh2[tid] += sh2[tid+st]; }
        __syncthreads();
    }
    float mean = sh[0] * (1.f/NPIX);
    float var = sh2[0] * (1.f/NPIX) - mean*mean;
    float inv = rsqrtf(var + EPSv);
    float sc = inv * nw[prm];
    float sh_ = nb[prm] - mean * sc;
    #pragma unroll
    for (int t = 0; t < 16; t++) {
        float4 u = v[t];
        u.x = fmaf(u.x, sc, sh_);
        u.y = fmaf(u.y, sc, sh_);
        u.z = fmaf(u.z, sc, sh_);
        u.w = fmaf(u.w, sc, sh_);
        p[tid + t*256] = u;
    }
}

// ---------------- gating ----------------
__global__ void gate_k(const float* __restrict__ g,
                       const float* __restrict__ gw0, const float* __restrict__ gb0,
                       const float* __restrict__ gw1, const float* __restrict__ gb1,
                       float* __restrict__ cof_out, int* __restrict__ sel,
                       float* __restrict__ cofsel)
{
    int b = threadIdx.x;
    if (b >= Bsz) return;
    float lg[4], noi[4];
    for (int e = 0; e < 4; e++) {
        float a0 = gb0[e], a1 = gb1[e];
        for (int c = 0; c < 64; c++) {
            float gv = g[b*64 + c];
            a0 += gw0[e*64 + c] * gv;
            a1 += gw1[e*64 + c] * gv;
        }
        lg[e] = a1 > 0.f ? a1 : LEAKv * a1;
        noi[e] = fmaxf(a0, 0.f) + log1pf(expf(-fabsf(a0)));
    }
    float m = 0.25f * (noi[0] + noi[1] + noi[2] + noi[3]);
    float var = 0.f;
    for (int e = 0; e < 4; e++) { float dd = noi[e] - m; var += dd*dd; }
    float sd = sqrtf(var / 3.f);
    float sc[4];
    for (int e = 0; e < 4; e++) sc[e] = lg[e] + (noi[e] - m) / sd;
    int i0 = 0;
    for (int e = 1; e < 4; e++) if (sc[e] > sc[i0]) i0 = e;
    int i1 = -1;
    for (int e = 0; e < 4; e++) {
        if (e == i0) continue;
        if (i1 < 0 || sc[e] > sc[i1]) i1 = e;
    }
    float mm = fmaxf(lg[i0], lg[i1]);
    float e0 = expf(lg[i0] - mm), e1 = expf(lg[i1] - mm);
    float c0 = e0 / (e0 + e1), c1 = e1 / (e0 + e1);
    if (cof_out) {
        for (int e = 0; e < 4; e++) cof_out[b*4 + e] = 0.f;
        cof_out[b*4 + i0] = c0;
        cof_out[b*4 + i1] = c1;
    }
    sel[b*2 + 0] = i0; sel[b*2 + 1] = i1;
    cofsel[b*2 + 0] = c0; cofsel[b*2 + 1] = c1;
}

// ---------------- launch ----------------
extern "C" void kernel_launch(void* const* d_in, const int* in_sizes, int n_in,
                              void* d_out, int out_size)
{
    const float* x       = (const float*)d_in[0];
    const float* winv    = (const float*)d_in[1];
    const float* blk_w1  = (const float*)d_in[2];
    const float* blk_b1  = (const float*)d_in[3];
    const float* blk_nw  = (const float*)d_in[4];
    const float* blk_nb  = (const float*)d_in[5];
    const float* blk_w2  = (const float*)d_in[6];
    const float* blk_b2  = (const float*)d_in[7];
    const float* fuse_w  = (const float*)d_in[8];
    const float* fuse_b  = (const float*)d_in[9];
    const float* gw0     = (const float*)d_in[10];
    const float* gb0     = (const float*)d_in[11];
    const float* gw1     = (const float*)d_in[12];
    const float* gb1     = (const float*)d_in[13];
    const float* ew1     = (const float*)d_in[14];
    const float* eb1     = (const float*)d_in[15];
    const float* ew2     = (const float*)d_in[16];
    const float* eb2     = (const float*)d_in[17];
    float* out = (float*)d_out;
    float* cof_out = ((size_t)out_size >= BS + Bsz*4) ? out + BS : nullptr;

    float *x1, *x2, *y1, *y2, *rb, *sb, *xf, *hb, *gv, *cofsel;
    int* sel; uint2* wpack; float2* part;
    void* p;
    cudaGetSymbolAddress(&p, g_x1);  x1 = (float*)p;
    cudaGetSymbolAddress(&p, g_x2);  x2 = (float*)p;
    cudaGetSymbolAddress(&p, g_y1);  y1 = (float*)p;
    cudaGetSymbolAddress(&p, g_y2);  y2 = (float*)p;
    cudaGetSymbolAddress(&p, g_rb);  rb = (float*)p;
    cudaGetSymbolAddress(&p, g_sb);  sb = (float*)p;
    cudaGetSymbolAddress(&p, g_xf);  xf = (float*)p;
    cudaGetSymbolAddress(&p, g_hb);  hb = (float*)p;
    cudaGetSymbolAddress(&p, g_gv);  gv = (float*)p;
    cudaGetSymbolAddress(&p, g_sel); sel = (int*)p;
    cudaGetSymbolAddress(&p, g_cofsel); cofsel = (float*)p;
    cudaGetSymbolAddress(&p, g_wpack);  wpack = (uint2*)p;
    cudaGetSymbolAddress(&p, g_part);   part = (float2*)p;

    dim3 cgrid(HWd/CTW, HWd/CTH, Bsz);
    dim3 cgrid2(HWd/CTW, HWd/CTH, Bsz*2);
    dim3 wgrid(NPIX/128, 2, Bsz);
    dim3 fgrid(NPIX/128, 1, Bsz);

    pack_all<<<(14*WSET+255)/256, 256>>>(blk_w1, blk_w2, ew1, ew2, wpack);

    // winv
    gemm1x1_mma<128,false><<<wgrid, 256>>>(x, nullptr, winv, nullptr, x1, x2, nullptr);

    // hin0(x2) -> y1
    conv3x3_mma<0><<<cgrid, 256>>>(x2, wpack + 0*WSET, blk_b1 + 0*64, rb,
                                   nullptr, nullptr, nullptr, nullptr, nullptr, nullptr);
    inorm_k<<<Bsz*32, 256>>>(rb, blk_nw + 0*32, blk_nb + 0*32);
    conv3x3_mma<1><<<cgrid, 256>>>(rb, wpack + 3*WSET, blk_b2 + 0*64, y1,
                                   x2, x1, nullptr, nullptr, nullptr, nullptr);

    // DUAL conv1 on y1: set0 -> rb (hin2, w1[2]); set1 -> hb (hin1, w1[1])
    conv3x3_mma<6><<<cgrid2, 256>>>(y1, wpack + 2*WSET, blk_b1 + 2*64, rb,
                                    nullptr, nullptr, nullptr, nullptr, nullptr, hb);
    // merged inorm: rb with set2 params, hb with set1 params
    inorm2_k<<<Bsz*32*2, 256>>>(rb, hb, blk_nw, blk_nb);

    // hin2 conv2 -> s_pre
    conv3x3_mma<2><<<cgrid, 256>>>(rb, wpack + 5*WSET, blk_b2 + 2*64, sb,
                                   y1, nullptr, nullptr, nullptr, nullptr, nullptr);
    // hin1 conv2 fused with flow -> y2
    conv3x3_mma<3><<<cgrid, 256>>>(hb, wpack + 4*WSET, blk_b2 + 1*64, y2,
                                   y1, x2, sb, nullptr, nullptr, nullptr);

    // fuse 1x1 with fused pool partials
    gemm1x1_mma<128,true><<<fgrid, 256>>>(y1, y2, fuse_w, fuse_b, xf, nullptr, part);

    pool2_k<<<Bsz*64, 128>>>(part, gv);
    gate_k<<<1, 32>>>(gv, gw0, gb0, gw1, gb1, cof_out, sel, cofsel);

    // experts
    conv3x3_mma<4><<<cgrid2, 256>>>(xf, wpack + 6*WSET, eb1, hb,
                                    nullptr, nullptr, nullptr, sel, cofsel, rb);
    conv3x3_mma<5><<<cgrid, 256>>>(hb, wpack + 10*WSET, eb2, out,
                                   xf, rb, nullptr, sel, cofsel, nullptr);
}

// round 17
// speedup vs baseline: 1.5012x; 1.5012x over previous
#include <cuda_runtime.h>
#include <math.h>

#define Bsz 8
#define Cc 64
#define HWd 128
#define NPIX (HWd*HWd)
#define PLANE ((size_t)Cc*NPIX)
#define BS ((size_t)Bsz*Cc*NPIX)
#define LEAKv 0.2f
#define CLAMPv 0.8f
#define EPSv 1e-5f
#define CWS (64*64*9)

#define CTW 16
#define CTH 8
#define INC 18
#define INREAL 180
#define INPAD 196
#define WPAD 68
#define SW_CH (36*WPAD)
#define WSET 18432

// ---------------- scratch ----------------
__device__ float g_x1[Bsz*Cc*NPIX];
__device__ float g_x2[Bsz*Cc*NPIX];
__device__ float g_y1[Bsz*Cc*NPIX];
__device__ float g_y2[Bsz*Cc*NPIX];
__device__ float g_rb[Bsz*Cc*NPIX];
__device__ float g_sb[Bsz*Cc*NPIX];
__device__ float g_xf[Bsz*Cc*NPIX];
__device__ float g_hb[Bsz*Cc*NPIX];
__device__ float g_gv[Bsz*Cc];
__device__ int   g_sel[Bsz*2];
__device__ float g_cofsel[Bsz*2];
__device__ uint2 g_wpack[14*WSET];
__device__ float2 g_part[Bsz*128*64];

__device__ __forceinline__ unsigned f2tf32(float f) {
    unsigned r;
    asm("cvt.rna.tf32.f32 %0, %1;" : "=r"(r) : "f"(f));
    return r;
}

__device__ __forceinline__ void mma_tf32(float* d, const unsigned* a, const unsigned* b) {
    asm volatile(
        "mma.sync.aligned.m16n8k8.row.col.f32.tf32.tf32.f32 "
        "{%0,%1,%2,%3}, {%4,%5,%6,%7}, {%8,%9}, {%0,%1,%2,%3};"
        : "+f"(d[0]), "+f"(d[1]), "+f"(d[2]), "+f"(d[3])
        : "r"(a[0]), "r"(a[1]), "r"(a[2]), "r"(a[3]), "r"(b[0]), "r"(b[1]));
}

__device__ __forceinline__ void cp_async8(unsigned sdst, const void* gsrc) {
    asm volatile("cp.async.ca.shared.global [%0], [%1], 8;" :: "r"(sdst), "l"(gsrc));
}
__device__ __forceinline__ void cp_commit() { asm volatile("cp.async.commit_group;" ::: "memory"); }
__device__ __forceinline__ void cp_wait1()  { asm volatile("cp.async.wait_group 1;" ::: "memory"); }
__device__ __forceinline__ void cp_wait0()  { asm volatile("cp.async.wait_group 0;" ::: "memory"); }

// ---------------- single merged weight repack ----------------
__global__ void pack_all(const float* __restrict__ w1, const float* __restrict__ w2,
                         const float* __restrict__ e1, const float* __restrict__ e2,
                         uint2* __restrict__ dst)
{
    int i = blockIdx.x*blockDim.x + threadIdx.x;
    if (i >= 14*WSET) return;
    int s = i / WSET;
    int r = i % WSET;
    const float* src;
    if (s < 3)       src = w1 + (size_t)s * CWS;
    else if (s < 6)  src = w2 + (size_t)(s-3) * CWS;
    else if (s < 10) src = e1 + (size_t)(s-6) * CWS;
    else             src = e2 + (size_t)(s-10) * CWS;
    int ck  = r / 2304;
    int rem = r % 2304;
    int q = rem >> 6, oc = rem & 63;
    int kq = q & 3, tap = q >> 2;
    int ic = ck*8 + kq;
    dst[i] = make_uint2(f2tf32(src[(oc*64 + ic)*9 + tap]),
                        f2tf32(src[(oc*64 + ic + 4)*9 + tap]));
}

// ---------------- 3x3 conv: TF32 MMA (R15 core, unchanged) ----------------
// MODE 0: out = conv+bias
// MODE 1: out = conv+bias+add1+add2
// MODE 2: out = conv+bias+add1
// MODE 3: out = conv+bias+add1 + add2*exp(clamp*(2sig(spre)-1))
// MODE 4: MERGED expert conv1: z=(slot*8+b); dst[slot] = cof*lrelu(conv+b_e)
// MODE 5: MERGED expert conv2: K=128 (in: 0-7, add2: 8-15), weights e0/e1 per half
template<int MODE>
__global__ __launch_bounds__(256, 3)
void conv3x3_mma(const float* __restrict__ in, const uint2* __restrict__ wpk,
                 const float* __restrict__ bias, float* __restrict__ out,
                 const float* __restrict__ add1, const float* __restrict__ add2,
                 const float* __restrict__ spre,
                 const int* __restrict__ sel, const float* __restrict__ cofsel,
                 float* __restrict__ out2)
{
    __shared__ uint2 s_in[4 * INPAD];
    __shared__ uint2 s_w[2 * SW_CH];

    const int NCK = (MODE == 5) ? 16 : 8;

    int tid = threadIdx.x;
    int wid = tid >> 5;
    int lane = tid & 31;
    int l4 = lane & 3;
    int g  = lane >> 2;
    int warp_m = wid & 3;
    int warp_n = wid >> 2;
    int wm2 = warp_m * 2;
    int n0 = warp_n * 32;

    int bz = blockIdx.z;
    int b    = (MODE == 4) ? (bz & 7) : bz;
    int slot = (MODE == 4) ? (bz >> 3) : 0;
    int w0 = blockIdx.x * CTW;
    int h0 = blockIdx.y * CTH;

    const uint2* wp  = wpk;
    const uint2* wp1 = nullptr;
    const float* bbase  = bias;
    const float* bbase1 = nullptr;
    float cw = 1.f, c0 = 0.f, c1 = 0.f;
    if (MODE == 4) {
        int e = sel[b*2 + slot];
        wp = wpk + e * WSET;
        bbase = bias + e * Cc;
        cw = cofsel[b*2 + slot];
    }
    if (MODE == 5) {
        int e0 = sel[b*2], e1 = sel[b*2 + 1];
        wp  = wpk + e0 * WSET;
        wp1 = wpk + e1 * WSET;
        bbase  = bias + e0 * Cc;
        bbase1 = bias + e1 * Cc;
        c0 = cofsel[b*2]; c1 = cofsel[b*2 + 1];
    }
    const float* inb0 = in + (size_t)b * PLANE;
    const float* inb1 = (MODE == 5) ? (add2 + (size_t)b * PLANE) : nullptr;

    unsigned wdst8[9];
    unsigned wsrc[9];
    unsigned swbase = (unsigned)__cvta_generic_to_shared(s_w);
    #pragma unroll
    for (int t = 0; t < 9; t++) {
        int i = tid + t*256;
        int q = i >> 6, oc = i & 63;
        wdst8[t] = (unsigned)((q*WPAD + oc) * 8);
        wsrc[t] = (unsigned)(q*64 + oc);
    }

    bool iact[3], ival[3];
    unsigned ioff[3];
    int ismem[3];
    #pragma unroll
    for (int t = 0; t < 3; t++) {
        int i = tid + t*256;
        iact[t] = (i < 4*INREAL);
        int kq  = i / INREAL;
        int rem = i - kq*INREAL;
        int rr = rem / INC;
        int cc = rem - rr*INC;
        int h = h0 - 1 + rr;
        int w = w0 - 1 + cc;
        ival[t] = iact[t] && ((unsigned)h < HWd) && ((unsigned)w < HWd);
        ismem[t] = kq*INPAD + rem;
        ioff[t] = ival[t] ? (unsigned)(kq*NPIX + h*HWd + w) : 0u;
    }

    float d[2][4][4];
    #pragma unroll
    for (int mt = 0; mt < 2; mt++)
        #pragma unroll
        for (int nt = 0; nt < 4; nt++)
            #pragma unroll
            for (int r = 0; r < 4; r++) d[mt][nt][r] = 0.f;

    #pragma unroll
    for (int t = 0; t < 9; t++)
        cp_async8(swbase + wdst8[t], wp + wsrc[t]);
    cp_commit();

    float ipf0[3], ipf1[3];
    #pragma unroll
    for (int t = 0; t < 3; t++) {
        ipf0[t] = ival[t] ? inb0[ioff[t]] : 0.f;
        ipf1[t] = ival[t] ? inb0[ioff[t] + 4*NPIX] : 0.f;
    }

    #pragma unroll 1
    for (int ck = 0; ck < NCK; ck++) {
        __syncthreads();
        #pragma unroll
        for (int t = 0; t < 3; t++)
            if (iact[t]) s_in[ismem[t]] = make_uint2(f2tf32(ipf0[t]), f2tf32(ipf1[t]));
        if (ck < NCK-1) {
            int nx = ck + 1;
            unsigned bufoff = (unsigned)((nx & 1) * SW_CH * 8);
            const uint2* srcw = ((MODE == 5 && nx >= 8) ? wp1 : wp) + (nx & 7) * 2304;
            #pragma unroll
            for (int t = 0; t < 9; t++)
                cp_async8(swbase + bufoff + wdst8[t], srcw + wsrc[t]);
            cp_commit();
            const float* srci = (MODE == 5 && nx >= 8) ? inb1 : inb0;
            unsigned ib = (unsigned)((nx & 7) * 8*NPIX);
            #pragma unroll
            for (int t = 0; t < 3; t++) {
                if (ival[t]) {
                    ipf0[t] = srci[ioff[t] + ib];
                    ipf1[t] = srci[ioff[t] + ib + 4*NPIX];
                }
            }
            cp_wait1();
        } else {
            cp_wait0();
        }
        __syncthreads();

        const uint2* swc = s_w + (ck&1)*SW_CH;
        #pragma unroll
        for (int tap = 0; tap < 9; tap++) {
            int ky = tap / 3, kx = tap % 3;
            int abase = l4*INPAD + (wm2 + ky)*INC + kx + g;
            unsigned a[2][4];
            #pragma unroll
            for (int mt = 0; mt < 2; mt++) {
                uint2 p0 = s_in[abase + mt*INC];
                uint2 p1 = s_in[abase + mt*INC + 8];
                a[mt][0] = p0.x; a[mt][1] = p1.x; a[mt][2] = p0.y; a[mt][3] = p1.y;
            }
            int bb = (tap*4 + l4)*WPAD + n0 + g;
            unsigned bq[4][2];
            #pragma unroll
            for (int nt = 0; nt < 4; nt++) {
                uint2 q = swc[bb + nt*8];
                bq[nt][0] = q.x; bq[nt][1] = q.y;
            }
            #pragma unroll
            for (int mt = 0; mt < 2; mt++)
                #pragma unroll
                for (int nt = 0; nt < 4; nt++)
                    mma_tf32(d[mt][nt], a[mt], bq[nt]);
        }
    }

    float csum = c0 + c1;
    float* dst4 = (MODE == 4 && slot) ? out2 : out;
    #pragma unroll
    for (int mt = 0; mt < 2; mt++) {
        int h = h0 + wm2 + mt;
        #pragma unroll
        for (int nt = 0; nt < 4; nt++) {
            int oc = n0 + nt*8 + l4*2;
            float bv0, bv1;
            if (MODE == 5) {
                bv0 = c0*bbase[oc]   + c1*bbase1[oc];
                bv1 = c0*bbase[oc+1] + c1*bbase1[oc+1];
            } else {
                bv0 = bbase[oc]; bv1 = bbase[oc+1];
            }
            size_t p0 = (size_t)b*PLANE + (size_t)oc*NPIX + (size_t)h*HWd;
            size_t p1 = p0 + NPIX;
            int wa = w0 + g, wb2 = wa + 8;
            float vv[4] = { d[mt][nt][0] + bv0, d[mt][nt][1] + bv1,
                            d[mt][nt][2] + bv0, d[mt][nt][3] + bv1 };
            size_t ix[4] = { p0 + wa, p1 + wa, p0 + wb2, p1 + wb2 };
            #pragma unroll
            for (int r = 0; r < 4; r++) {
                size_t idx = ix[r];
                float v = vv[r];
                if (MODE == 1) {
                    v += add1[idx] + add2[idx];
                } else if (MODE == 2) {
                    v += add1[idx];
                } else if (MODE == 3) {
                    float sp = spre[idx];
                    float sig = 1.f / (1.f + expf(-sp));
                    float s = CLAMPv * (2.f*sig - 1.f);
                    v += add1[idx] + add2[idx] * expf(s);
                } else if (MODE == 4) {
                    v = v > 0.f ? v : LEAKv * v;
                    v *= cw;
                } else if (MODE == 5) {
                    v += csum * add1[idx];
                }
                if (MODE == 4) dst4[idx] = v;
                else           out[idx] = v;
            }
        }
    }
}

// ---------------- 1x1 GEMM via TF32 MMA (+ compile-time POOL partials) ----------------
#define GPAD 132

template<int IC, bool POOL>
__global__ __launch_bounds__(256)
void gemm1x1_mma(const float* __restrict__ inA, const float* __restrict__ inB,
                 const float* __restrict__ W, const float* __restrict__ bias,
                 float* __restrict__ outA, float* __restrict__ outB,
                 float2* __restrict__ gpart)
{
    __shared__ uint2 s_x[8 * GPAD];
    __shared__ uint2 s_w[8 * WPAD];
    __shared__ float spm[8*32], sps[8*32];

    const int NCK = IC / 16;

    int tid = threadIdx.x;
    int wid = tid >> 5;
    int lane = tid & 31;
    int l4 = lane & 3;
    int g  = lane >> 2;
    int warp_m = wid & 3;
    int warp_n = wid >> 2;
    int n0 = warp_n * 32;

    int b   = blockIdx.z;
    int oc0 = blockIdx.y * 64;
    int p0  = blockIdx.x * 128;

    int axsm[4];
    unsigned aoff[4];
    #pragma unroll
    for (int t = 0; t < 4; t++) {
        int i = tid + t*256;
        int q = i >> 7, p = i & 127;
        int qoff = (q >> 2)*8 + (q & 3);
        axsm[t] = q*GPAD + p;
        aoff[t] = (unsigned)(qoff*NPIX + p0 + p);
    }
    int wxsm[2];
    unsigned woff0[2];
    #pragma unroll
    for (int t = 0; t < 2; t++) {
        int i = tid + t*256;
        int q = i & 7, oc = i >> 3;
        int qoff = (q >> 2)*8 + (q & 3);
        wxsm[t] = q*WPAD + oc;
        woff0[t] = (unsigned)((oc0 + oc)*IC + qoff);
    }

    const float* baseA = inA + ((size_t)b * (inB ? PLANE : (size_t)IC*NPIX));
    const float* baseB = inB ? (inB + (size_t)b * PLANE) : nullptr;

    float d[2][4][4];
    #pragma unroll
    for (int mt = 0; mt < 2; mt++)
        #pragma unroll
        for (int nt = 0; nt < 4; nt++)
            #pragma unroll
            for (int r = 0; r < 4; r++) d[mt][nt][r] = 0.f;

    float apf0[4], apf1[4], wpf0[2], wpf1[2];
    {
        const float* src = baseA;
        #pragma unroll
        for (int t = 0; t < 4; t++) {
            apf0[t] = src[aoff[t]];
            apf1[t] = src[aoff[t] + 4*NPIX];
        }
        #pragma unroll
        for (int t = 0; t < 2; t++) {
            wpf0[t] = W[woff0[t]];
            wpf1[t] = W[woff0[t] + 4];
        }
    }

    #pragma unroll 1
    for (int ck = 0; ck < NCK; ck++) {
        __syncthreads();
        #pragma unroll
        for (int t = 0; t < 4; t++)
            s_x[axsm[t]] = make_uint2(f2tf32(apf0[t]), f2tf32(apf1[t]));
        #pragma unroll
        for (int t = 0; t < 2; t++)
            s_w[wxsm[t]] = make_uint2(f2tf32(wpf0[t]), f2tf32(wpf1[t]));
        if (ck < NCK-1) {
            int nx = ck + 1;
            const float* src = (baseB && nx >= 4) ? baseB : baseA;
            unsigned chrel;
            if (baseB) chrel = (unsigned)(((nx & 3) * 16) * NPIX);
            else       chrel = (unsigned)(nx * 16 * NPIX);
            #pragma unroll
            for (int t = 0; t < 4; t++) {
                apf0[t] = src[chrel + aoff[t]];
                apf1[t] = src[chrel + aoff[t] + 4*NPIX];
            }
            unsigned wb = (unsigned)(nx * 16);
            #pragma unroll
            for (int t = 0; t < 2; t++) {
                wpf0[t] = W[woff0[t] + wb];
                wpf1[t] = W[woff0[t] + wb + 4];
            }
        }
        __syncthreads();

        #pragma unroll
        for (int ks = 0; ks < 2; ks++) {
            int abase = (ks*4 + l4)*GPAD + warp_m*32 + g;
            unsigned a[2][4];
            #pragma unroll
            for (int mt = 0; mt < 2; mt++) {
                uint2 q0 = s_x[abase + mt*16];
                uint2 q1 = s_x[abase + mt*16 + 8];
                a[mt][0] = q0.x; a[mt][1] = q1.x; a[mt][2] = q0.y; a[mt][3] = q1.y;
            }
            int bb = (ks*4 + l4)*WPAD + n0 + g;
            unsigned bq[4][2];
            #pragma unroll
            for (int nt = 0; nt < 4; nt++) {
                uint2 q = s_w[bb + nt*8];
                bq[nt][0] = q.x; bq[nt][1] = q.y;
            }
            #pragma unroll
            for (int mt = 0; mt < 2; mt++)
                #pragma unroll
                for (int nt = 0; nt < 4; nt++)
                    mma_tf32(d[mt][nt], a[mt], bq[nt]);
        }
    }

    float pm[4][2], ps[4][2];
    if (POOL) {
        #pragma unroll
        for (int nt = 0; nt < 4; nt++)
            #pragma unroll
            for (int j = 0; j < 2; j++) { pm[nt][j] = -1e30f; ps[nt][j] = 0.f; }
    }

    #pragma unroll
    for (int mt = 0; mt < 2; mt++) {
        #pragma unroll
        for (int nt = 0; nt < 4; nt++) {
            int oc = oc0 + n0 + nt*8 + l4*2;
            float bv0 = bias ? bias[oc] : 0.f;
            float bv1 = bias ? bias[oc+1] : 0.f;
            float* dst = outA;
            int ocd = oc;
            if (outB != nullptr && oc >= 64) { dst = outB; ocd = oc - 64; }
            int pix = p0 + warp_m*32 + mt*16 + g;
            size_t q0 = (size_t)b*PLANE + (size_t)ocd*NPIX + pix;
            size_t q1 = q0 + NPIX;
            float v0 = d[mt][nt][0] + bv0;
            float v1 = d[mt][nt][1] + bv1;
            float v2 = d[mt][nt][2] + bv0;
            float v3 = d[mt][nt][3] + bv1;
            dst[q0]     = v0;
            dst[q1]     = v1;
            dst[q0 + 8] = v2;
            dst[q1 + 8] = v3;
            if (POOL) {
                pm[nt][0] = fmaxf(pm[nt][0], fmaxf(v0, v2));
                pm[nt][1] = fmaxf(pm[nt][1], fmaxf(v1, v3));
                ps[nt][0] += v0 + v2;
                ps[nt][1] += v1 + v3;
            }
        }
    }

    if (POOL) {
        #pragma unroll
        for (int m = 4; m <= 16; m <<= 1) {
            #pragma unroll
            for (int nt = 0; nt < 4; nt++)
                #pragma unroll
                for (int j = 0; j < 2; j++) {
                    pm[nt][j] = fmaxf(pm[nt][j], __shfl_xor_sync(0xFFFFFFFF, pm[nt][j], m));
                    ps[nt][j] += __shfl_xor_sync(0xFFFFFFFF, ps[nt][j], m);
                }
        }
        if (g == 0) {
            #pragma unroll
            for (int nt = 0; nt < 4; nt++)
                #pragma unroll
                for (int j = 0; j < 2; j++) {
                    int ol = nt*8 + l4*2 + j;
                    spm[wid*32 + ol] = pm[nt][j];
                    sps[wid*32 + ol] = ps[nt][j];
                }
        }
        __syncthreads();
        if (tid < 64) {
            int oc = tid;
            int wn = oc >> 5, ol = oc & 31;
            float mx = -1e30f, sm = 0.f;
            #pragma unroll
            for (int wm = 0; wm < 4; wm++) {
                mx = fmaxf(mx, spm[(wn*4 + wm)*32 + ol]);
                sm += sps[(wn*4 + wm)*32 + ol];
            }
            gpart[((size_t)b*128 + blockIdx.x)*64 + oc] = make_float2(mx, sm);
        }
    }
}

// ---------------- pool partial reduce ----------------
__global__ __launch_bounds__(128)
void pool2_k(const float2* __restrict__ part, float* __restrict__ gv)
{
    int bidx = blockIdx.x;
    int b = bidx >> 6, oc = bidx & 63;
    int tid = threadIdx.x;
    float2 v = part[((size_t)b*128 + tid)*64 + oc];
    __shared__ float smx[128], ssm[128];
    smx[tid] = v.x; ssm[tid] = v.y;
    __syncthreads();
    for (int st = 64; st; st >>= 1) {
        if (tid < st) { smx[tid] = fmaxf(smx[tid], smx[tid+st]); ssm[tid] += ssm[tid+st]; }
        __syncthreads();
    }
    if (tid == 0) gv[bidx] = smx[0] + ssm[0] * (1.f/NPIX);
}

// ---------------- instance norm (in-place, float4, unrolled — R15) ----------------
__global__ __launch_bounds__(256)
void inorm_k(float* __restrict__ r, const float* __restrict__ nw, const float* __restrict__ nb)
{
    int bidx = blockIdx.x;
    int b = bidx >> 5, c = bidx & 31;
    float4* p = (float4*)(r + (size_t)b*PLANE + (size_t)c*NPIX);
    int tid = threadIdx.x;
    float4 v[16];
    #pragma unroll
    for (int t = 0; t < 16; t++) v[t] = p[tid + t*256];
    float s = 0.f, s2 = 0.f;
    #pragma unroll
    for (int t = 0; t < 16; t++) {
        s  += (v[t].x + v[t].y) + (v[t].z + v[t].w);
        s2 += (v[t].x*v[t].x + v[t].y*v[t].y) + (v[t].z*v[t].z + v[t].w*v[t].w);
    }
    __shared__ float sh[256], sh2[256];
    sh[tid] = s; sh2[tid] = s2;
    __syncthreads();
    for (int st = 128; st; st >>= 1) {
        if (tid < st) { sh[tid] += sh[tid+st]; sh2[tid] += sh2[tid+st]; }
        __syncthreads();
    }
    float mean = sh[0] * (1.f/NPIX);
    float var = sh2[0] * (1.f/NPIX) - mean*mean;
    float inv = rsqrtf(var + EPSv);
    float sc = inv * nw[c];
    float sh_ = nb[c] - mean * sc;
    #pragma unroll
    for (int t = 0; t < 16; t++) {
        float4 u = v[t];
        u.x = fmaf(u.x, sc, sh_);
        u.y = fmaf(u.y, sc, sh_);
        u.z = fmaf(u.z, sc, sh_);
        u.w = fmaf(u.w, sc, sh_);
        p[tid + t*256] = u;
    }
}

// ---------------- gating ----------------
__global__ void gate_k(const float* __restrict__ g,
                       const float* __restrict__ gw0, const float* __restrict__ gb0,
                       const float* __restrict__ gw1, const float* __restrict__ gb1,
                       float* __restrict__ cof_out, int* __restrict__ sel,
                       float* __restrict__ cofsel)
{
    int b = threadIdx.x;
    if (b >= Bsz) return;
    float lg[4], noi[4];
    for (int e = 0; e < 4; e++) {
        float a0 = gb0[e], a1 = gb1[e];
        for (int c = 0; c < 64; c++) {
            float gv = g[b*64 + c];
            a0 += gw0[e*64 + c] * gv;
            a1 += gw1[e*64 + c] * gv;
        }
        lg[e] = a1 > 0.f ? a1 : LEAKv * a1;
        noi[e] = fmaxf(a0, 0.f) + log1pf(expf(-fabsf(a0)));
    }
    float m = 0.25f * (noi[0] + noi[1] + noi[2] + noi[3]);
    float var = 0.f;
    for (int e = 0; e < 4; e++) { float dd = noi[e] - m; var += dd*dd; }
    float sd = sqrtf(var / 3.f);
    float sc[4];
    for (int e = 0; e < 4; e++) sc[e] = lg[e] + (noi[e] - m) / sd;
    int i0 = 0;
    for (int e = 1; e < 4; e++) if (sc[e] > sc[i0]) i0 = e;
    int i1 = -1;
    for (int e = 0; e < 4; e++) {
        if (e == i0) continue;
        if (i1 < 0 || sc[e] > sc[i1]) i1 = e;
    }
    float mm = fmaxf(lg[i0], lg[i1]);
    float e0 = expf(lg[i0] - mm), e1 = expf(lg[i1] - mm);
    float c0 = e0 / (e0 + e1), c1 = e1 / (e0 + e1);
    if (cof_out) {
        for (int e = 0; e < 4; e++) cof_out[b*4 + e] = 0.f;
        cof_out[b*4 + i0] = c0;
        cof_out[b*4 + i1] = c1;
    }
    sel[b*2 + 0] = i0; sel[b*2 + 1] = i1;
    cofsel[b*2 + 0] = c0; cofsel[b*2 + 1] = c1;
}

// ---------------- launch ----------------
extern "C" void kernel_launch(void* const* d_in, const int* in_sizes, int n_in,
                              void* d_out, int out_size)
{
    const float* x       = (const float*)d_in[0];
    const float* winv    = (const float*)d_in[1];
    const float* blk_w1  = (const float*)d_in[2];
    const float* blk_b1  = (const float*)d_in[3];
    const float* blk_nw  = (const float*)d_in[4];
    const float* blk_nb  = (const float*)d_in[5];
    const float* blk_w2  = (const float*)d_in[6];
    const float* blk_b2  = (const float*)d_in[7];
    const float* fuse_w  = (const float*)d_in[8];
    const float* fuse_b  = (const float*)d_in[9];
    const float* gw0     = (const float*)d_in[10];
    const float* gb0     = (const float*)d_in[11];
    const float* gw1     = (const float*)d_in[12];
    const float* gb1     = (const float*)d_in[13];
    const float* ew1     = (const float*)d_in[14];
    const float* eb1     = (const float*)d_in[15];
    const float* ew2     = (const float*)d_in[16];
    const float* eb2     = (const float*)d_in[17];
    float* out = (float*)d_out;
    float* cof_out = ((size_t)out_size >= BS + Bsz*4) ? out + BS : nullptr;

    float *x1, *x2, *y1, *y2, *rb, *sb, *xf, *hb, *gv, *cofsel;
    int* sel; uint2* wpack; float2* part;
    void* p;
    cudaGetSymbolAddress(&p, g_x1);  x1 = (float*)p;
    cudaGetSymbolAddress(&p, g_x2);  x2 = (float*)p;
    cudaGetSymbolAddress(&p, g_y1);  y1 = (float*)p;
    cudaGetSymbolAddress(&p, g_y2);  y2 = (float*)p;
    cudaGetSymbolAddress(&p, g_rb);  rb = (float*)p;
    cudaGetSymbolAddress(&p, g_sb);  sb = (float*)p;
    cudaGetSymbolAddress(&p, g_xf);  xf = (float*)p;
    cudaGetSymbolAddress(&p, g_hb);  hb = (float*)p;
    cudaGetSymbolAddress(&p, g_gv);  gv = (float*)p;
    cudaGetSymbolAddress(&p, g_sel); sel = (int*)p;
    cudaGetSymbolAddress(&p, g_cofsel); cofsel = (float*)p;
    cudaGetSymbolAddress(&p, g_wpack);  wpack = (uint2*)p;
    cudaGetSymbolAddress(&p, g_part);   part = (float2*)p;

    dim3 cgrid(HWd/CTW, HWd/CTH, Bsz);
    dim3 cgrid4(HWd/CTW, HWd/CTH, Bsz*2);
    dim3 wgrid(NPIX/128, 2, Bsz);
    dim3 fgrid(NPIX/128, 1, Bsz);

    pack_all<<<(14*WSET+255)/256, 256>>>(blk_w1, blk_w2, ew1, ew2, wpack);

    gemm1x1_mma<128,false><<<wgrid, 256>>>(x, nullptr, winv, nullptr, x1, x2, nullptr);

    conv3x3_mma<0><<<cgrid, 256>>>(x2, wpack + 0*WSET, blk_b1 + 0*64, rb,
                                   nullptr, nullptr, nullptr, nullptr, nullptr, nullptr);
    inorm_k<<<Bsz*32, 256>>>(rb, blk_nw + 0*32, blk_nb + 0*32);
    conv3x3_mma<1><<<cgrid, 256>>>(rb, wpack + 3*WSET, blk_b2 + 0*64, y1,
                                   x2, x1, nullptr, nullptr, nullptr, nullptr);

    conv3x3_mma<0><<<cgrid, 256>>>(y1, wpack + 2*WSET, blk_b1 + 2*64, rb,
                                   nullptr, nullptr, nullptr, nullptr, nullptr, nullptr);
    inorm_k<<<Bsz*32, 256>>>(rb, blk_nw + 2*32, blk_nb + 2*32);
    conv3x3_mma<2><<<cgrid, 256>>>(rb, wpack + 5*WSET, blk_b2 + 2*64, sb,
                                   y1, nullptr, nullptr, nullptr, nullptr, nullptr);

    conv3x3_mma<0><<<cgrid, 256>>>(y1, wpack + 1*WSET, blk_b1 + 1*64, rb,
                                   nullptr, nullptr, nullptr, nullptr, nullptr, nullptr);
    inorm_k<<<Bsz*32, 256>>>(rb, blk_nw + 1*32, blk_nb + 1*32);
    conv3x3_mma<3><<<cgrid, 256>>>(rb, wpack + 4*WSET, blk_b2 + 1*64, y2,
                                   y1, x2, sb, nullptr, nullptr, nullptr);

    // fuse 1x1 with fused pool partials (the ONE change vs R15)
    gemm1x1_mma<128,true><<<fgrid, 256>>>(y1, y2, fuse_w, fuse_b, xf, nullptr, part);

    pool2_k<<<Bsz*64, 128>>>(part, gv);
    gate_k<<<1, 32>>>(gv, gw0, gb0, gw1, gb1, cof_out, sel, cofsel);

    conv3x3_mma<4><<<cgrid4, 256>>>(xf, wpack + 6*WSET, eb1, hb,
                                    nullptr, nullptr, nullptr, sel, cofsel, rb);
    conv3x3_mma<5><<<cgrid, 256>>>(hb, wpack + 10*WSET, eb2, out,
                                   xf, rb, nullptr, sel, cofsel, nullptr);
}